// round 12
// baseline (speedup 1.0000x reference)
#include <cuda_runtime.h>

// Deriv2Matern52: out[i,a,j,b] = c^2 * ( (a==b)*A(i,j)*inv_l2[a] - 5*fr(i,j)*D[i,j,a]*D[i,j,b] )
//
// A-major store-ordering variant (DRAM burst-locality experiment):
//   phase 1: JT=256 threads compute per-(i,j) pair data into smem (as champion)
//   phase 2: 16 warps; warp w owns a = w/2 and half the j-tile. Each lane
//            writes 4 j-rows via st.global.cs.v8.f32 (32B each); a warp
//            instruction covers 1KB contiguous, and a warp's 4 iterations walk
//            one contiguous 4KB region (long DRAM bursts instead of 512B
//            scattered across 8 regions 32KB apart).

#define D_DIM 8
#define JT 256          // j-tile per block (phase1 threads)
#define NTHREADS 512    // 16 warps
#define SSTRIDE 17      // smem row stride in floats (coprime with 32 banks)
#define SQRT5F 2.2360679774997896f

__device__ __forceinline__ void stg256_cs(float* p,
    float o0, float o1, float o2, float o3,
    float o4, float o5, float o6, float o7)
{
    asm volatile(
        "st.global.cs.v8.f32 [%0], {%1,%2,%3,%4,%5,%6,%7,%8};"
        :: "l"(p),
           "f"(o0), "f"(o1), "f"(o2), "f"(o3),
           "f"(o4), "f"(o5), "f"(o6), "f"(o7)
        : "memory");
}

__global__ __launch_bounds__(NTHREADS) void deriv2_matern52_kernel(
    const float* __restrict__ X1,   // [n, 8]
    const float* __restrict__ X2,   // [m, 8]
    const float* __restrict__ cptr, // [1]
    const float* __restrict__ lptr, // [8]
    float* __restrict__ out,        // [n, 8, m, 8]
    int m)
{
    __shared__ float sp[JT * SSTRIDE];
    // sp[p*17 + 0..7]  = Dv[a]      (dx[a] * inv_l2[a])
    // sp[p*17 + 8]     = -5 * fr * c^2
    // sp[p*17 + 9..16] = A * c^2 * inv_l2[a]   (diagonal terms)

    const int t  = threadIdx.x;
    const int i  = blockIdx.y;
    const int j0 = blockIdx.x * JT;

    // ---------------- phase 1: pair data ----------------
    if (t < JT) {
        float invl2[D_DIM];
#pragma unroll
        for (int a = 0; a < D_DIM; a++) {
            float lv = __ldg(lptr + a);
            invl2[a] = 1.0f / (lv * lv);
        }
        float cv = __ldg(cptr);
        float c2 = cv * cv;

        const float4* x1p = reinterpret_cast<const float4*>(X1 + (size_t)i * D_DIM);
        const float4* x2p = reinterpret_cast<const float4*>(X2 + (size_t)(j0 + t) * D_DIM);
        float4 x1a = __ldg(x1p);
        float4 x1b = __ldg(x1p + 1);
        float4 x2a = __ldg(x2p);
        float4 x2b = __ldg(x2p + 1);

        float dx[D_DIM];
        dx[0] = x1a.x - x2a.x; dx[1] = x1a.y - x2a.y;
        dx[2] = x1a.z - x2a.z; dx[3] = x1a.w - x2a.w;
        dx[4] = x1b.x - x2b.x; dx[5] = x1b.y - x2b.y;
        dx[6] = x1b.z - x2b.z; dx[7] = x1b.w - x2b.w;

        float s = 0.0f;
        float* row = sp + t * SSTRIDE;
#pragma unroll
        for (int a = 0; a < D_DIM; a++) {
            float dv = dx[a] * invl2[a];
            row[a] = dv;
            s = fmaf(dx[a], dv, s);
        }
        float r   = sqrtf(s);
        float fr  = (5.0f / 3.0f) * expf(-SQRT5F * r);
        float A   = fr * fmaf(SQRT5F, r, 1.0f);
        float Ac2 = A * c2;
        row[8] = -5.0f * fr * c2;
#pragma unroll
        for (int a = 0; a < D_DIM; a++)
            row[9 + a] = Ac2 * invl2[a];
    }
    __syncthreads();

    // ---------------- phase 2: a-major contiguous stores ----------------
    // warp w (0..15): a = w>>1, j sub-range = (w&1)*128; lane handles 4 j's.
    const int w    = t >> 5;
    const int lane = t & 31;
    const int a    = w >> 1;
    const int jsub = (w & 1) * (JT / 2);

    // base of slice (i, a, j0+jsub, 0)
    float* dst = out + ((((size_t)i * D_DIM + a) * (size_t)m + (size_t)(j0 + jsub)) * D_DIM);

#pragma unroll
    for (int k = 0; k < 4; k++) {
        const int jj = jsub + k * 32 + lane;          // j within tile
        const float* row = sp + jj * SSTRIDE;

        float Dva = row[a];
        float m5  = row[8];
        float ta  = m5 * Dva;

        float o0 = ta * row[0];
        float o1 = ta * row[1];
        float o2 = ta * row[2];
        float o3 = ta * row[3];
        float o4 = ta * row[4];
        float o5 = ta * row[5];
        float o6 = ta * row[6];
        float o7 = ta * row[7];
        float add = row[9 + a];
        switch (a) {
            case 0: o0 += add; break;
            case 1: o1 += add; break;
            case 2: o2 += add; break;
            case 3: o3 += add; break;
            case 4: o4 += add; break;
            case 5: o5 += add; break;
            case 6: o6 += add; break;
            case 7: o7 += add; break;
        }
        stg256_cs(dst + (size_t)(k * 32 + lane) * D_DIM,
                  o0, o1, o2, o3, o4, o5, o6, o7);
    }
}

extern "C" void kernel_launch(void* const* d_in, const int* in_sizes, int n_in,
                              void* d_out, int out_size)
{
    const float* X1 = (const float*)d_in[0];
    const float* X2 = (const float*)d_in[1];
    const float* c  = (const float*)d_in[2];
    const float* l  = (const float*)d_in[3];
    float* out = (float*)d_out;

    int n = in_sizes[0] / D_DIM;
    int m = in_sizes[1] / D_DIM;

    dim3 grid(m / JT, n);
    deriv2_matern52_kernel<<<grid, NTHREADS>>>(X1, X2, c, l, out, m);
}